// round 1
// baseline (speedup 1.0000x reference)
#include <cuda_runtime.h>

#define SEQ   4096
#define DIM   512
#define NHEAD 8
#define HD    64
#define SCALE 0.125f   // 1/sqrt(64)

// Scratch (allocation-free contract: __device__ globals)
__device__ float g_Q[SEQ * DIM];
__device__ float g_K[SEQ * DIM];
__device__ float g_V[SEQ * DIM];
__device__ float g_O[SEQ * DIM];

// ---------------------------------------------------------------------------
// GEMM: C[SEQ,DIM] = A[SEQ,DIM] @ B[DIM,DIM]^T   (both operands K-contiguous)
// 64x64 tile, 256 threads, 4x4 microtile, BK=16, 1-deep register prefetch.
// ---------------------------------------------------------------------------
__device__ __forceinline__ void gemm_body(const float* __restrict__ A,
                                          const float* __restrict__ B,
                                          float* __restrict__ C) {
    __shared__ float As[16][68];   // As[k][m], pad keeps 16B alignment + banks spread
    __shared__ float Bs[16][68];   // Bs[k][n]
    const int tid  = threadIdx.x;
    const int tx   = tid & 15;
    const int ty   = tid >> 4;
    const int bm   = blockIdx.y * 64;
    const int bn   = blockIdx.x * 64;
    const int lrow = tid >> 2;          // 0..63
    const int lk   = (tid & 3) << 2;    // 0,4,8,12

    const float* Ap = A + (bm + lrow) * DIM + lk;
    const float* Bp = B + (bn + lrow) * DIM + lk;

    float acc[4][4] = {};
    float4 a = *(const float4*)Ap;
    float4 b = *(const float4*)Bp;

    for (int k0 = 0; k0 < DIM; k0 += 16) {
        __syncthreads();
        As[lk + 0][lrow] = a.x; As[lk + 1][lrow] = a.y;
        As[lk + 2][lrow] = a.z; As[lk + 3][lrow] = a.w;
        Bs[lk + 0][lrow] = b.x; Bs[lk + 1][lrow] = b.y;
        Bs[lk + 2][lrow] = b.z; Bs[lk + 3][lrow] = b.w;
        __syncthreads();
        if (k0 + 16 < DIM) {                   // prefetch next K-slab
            a = *(const float4*)(Ap + k0 + 16);
            b = *(const float4*)(Bp + k0 + 16);
        }
        #pragma unroll
        for (int kk = 0; kk < 16; kk++) {
            float av[4], bv[4];
            #pragma unroll
            for (int i = 0; i < 4; i++) av[i] = As[kk][ty * 4 + i];
            #pragma unroll
            for (int j = 0; j < 4; j++) bv[j] = Bs[kk][tx * 4 + j];
            #pragma unroll
            for (int i = 0; i < 4; i++)
                #pragma unroll
                for (int j = 0; j < 4; j++)
                    acc[i][j] = fmaf(av[i], bv[j], acc[i][j]);
        }
    }
    #pragma unroll
    for (int i = 0; i < 4; i++) {
        float4 v = make_float4(acc[i][0], acc[i][1], acc[i][2], acc[i][3]);
        *(float4*)(C + (bm + ty * 4 + i) * DIM + bn + tx * 4) = v;
    }
}

// dst: 0->g_Q, 1->g_K, 2->g_V  (device-side select; no symbol lookups on host)
__global__ void __launch_bounds__(256)
gemm_proj_kernel(const float* __restrict__ x, const float* __restrict__ W, int dst) {
    float* C = (dst == 0) ? g_Q : (dst == 1) ? g_K : g_V;
    gemm_body(x, W, C);
}

__global__ void __launch_bounds__(256)
gemm_out_kernel(const float* __restrict__ Wo, float* __restrict__ out) {
    gemm_body(g_O, Wo, out);
}

// ---------------------------------------------------------------------------
// Flash-style attention: one block = 64 query rows of one head, streams K/V in
// 64-row tiles with online softmax. 256 threads as a 16x16 grid of 4x4 tiles.
// Row statistics reduced across the 16 lanes sharing a row (shfl_xor 1,2,4,8).
// ---------------------------------------------------------------------------
#define ATT_SMEM (4 * 64 * 65 * (int)sizeof(float))   // Qs,Ks,Vs,Ps = 66560 B

__global__ void __launch_bounds__(256) attn_kernel() {
    extern __shared__ float sm[];
    float* Qs = sm;                 // [64][65]
    float* Ks = sm + 64 * 65;
    float* Vs = sm + 2 * 64 * 65;
    float* Ps = sm + 3 * 64 * 65;

    const int tid  = threadIdx.x;
    const int tx   = tid & 15;
    const int ty   = tid >> 4;
    const int qb   = blockIdx.x;
    const int h    = blockIdx.y;
    const int col0 = h * HD;

    // Load Q tile (64x64) once
    #pragma unroll
    for (int it = 0; it < 4; it++) {
        int lin = tid + it * 256;
        int row = lin >> 4;
        int c4  = (lin & 15) << 2;
        float4 v = *(const float4*)&g_Q[(qb * 64 + row) * DIM + col0 + c4];
        float* qd = &Qs[row * 65 + c4];
        qd[0] = v.x; qd[1] = v.y; qd[2] = v.z; qd[3] = v.w;
    }

    float acc[4][4] = {};
    float m_i[4], l_i[4];
    #pragma unroll
    for (int i = 0; i < 4; i++) { m_i[i] = -1e30f; l_i[i] = 0.f; }

    // Register prefetch of K/V tile kb=0
    float4 kreg[4], vreg[4];
    #pragma unroll
    for (int it = 0; it < 4; it++) {
        int lin = tid + it * 256;
        int row = lin >> 4;
        int c4  = (lin & 15) << 2;
        int g   = row * DIM + col0 + c4;
        kreg[it] = *(const float4*)&g_K[g];
        vreg[it] = *(const float4*)&g_V[g];
    }

    for (int kb = 0; kb < SEQ / 64; kb++) {
        __syncthreads();   // prior iteration's Ks/Vs/Ps consumers done
        #pragma unroll
        for (int it = 0; it < 4; it++) {
            int lin = tid + it * 256;
            int row = lin >> 4;
            int c4  = (lin & 15) << 2;
            float* kd = &Ks[row * 65 + c4];
            kd[0] = kreg[it].x; kd[1] = kreg[it].y; kd[2] = kreg[it].z; kd[3] = kreg[it].w;
            float* vd = &Vs[row * 65 + c4];
            vd[0] = vreg[it].x; vd[1] = vreg[it].y; vd[2] = vreg[it].z; vd[3] = vreg[it].w;
        }
        __syncthreads();
        if (kb + 1 < SEQ / 64) {           // prefetch next tile; overlaps compute
            #pragma unroll
            for (int it = 0; it < 4; it++) {
                int lin = tid + it * 256;
                int row = lin >> 4;
                int c4  = (lin & 15) << 2;
                int g   = ((kb + 1) * 64 + row) * DIM + col0 + c4;
                kreg[it] = *(const float4*)&g_K[g];
                vreg[it] = *(const float4*)&g_V[g];
            }
        }

        // S = Q @ K^T (64x64x64)
        float s[4][4] = {};
        #pragma unroll 16
        for (int d = 0; d < HD; d++) {
            float qv[4], kv[4];
            #pragma unroll
            for (int i = 0; i < 4; i++) qv[i] = Qs[(ty * 4 + i) * 65 + d];
            #pragma unroll
            for (int j = 0; j < 4; j++) kv[j] = Ks[(tx * 4 + j) * 65 + d];
            #pragma unroll
            for (int i = 0; i < 4; i++)
                #pragma unroll
                for (int j = 0; j < 4; j++)
                    s[i][j] = fmaf(qv[i], kv[j], s[i][j]);
        }

        // Online softmax update (per row; 16 lanes share a row)
        #pragma unroll
        for (int i = 0; i < 4; i++) {
            #pragma unroll
            for (int j = 0; j < 4; j++) s[i][j] *= SCALE;
            float mx = fmaxf(fmaxf(s[i][0], s[i][1]), fmaxf(s[i][2], s[i][3]));
            mx = fmaxf(mx, __shfl_xor_sync(0xffffffffu, mx, 1));
            mx = fmaxf(mx, __shfl_xor_sync(0xffffffffu, mx, 2));
            mx = fmaxf(mx, __shfl_xor_sync(0xffffffffu, mx, 4));
            mx = fmaxf(mx, __shfl_xor_sync(0xffffffffu, mx, 8));
            float m_new = fmaxf(m_i[i], mx);
            float alpha = __expf(m_i[i] - m_new);
            float rs = 0.f;
            float* prow = &Ps[(ty * 4 + i) * 65 + tx * 4];
            #pragma unroll
            for (int j = 0; j < 4; j++) {
                float p = __expf(s[i][j] - m_new);
                prow[j] = p;
                rs += p;
            }
            rs += __shfl_xor_sync(0xffffffffu, rs, 1);
            rs += __shfl_xor_sync(0xffffffffu, rs, 2);
            rs += __shfl_xor_sync(0xffffffffu, rs, 4);
            rs += __shfl_xor_sync(0xffffffffu, rs, 8);
            l_i[i] = l_i[i] * alpha + rs;
            m_i[i] = m_new;
            #pragma unroll
            for (int j = 0; j < 4; j++) acc[i][j] *= alpha;
        }
        __syncthreads();   // Ps fully written before P@V

        // acc += P @ V (64x64x64)
        #pragma unroll 16
        for (int k = 0; k < 64; k++) {
            float pv[4], vv[4];
            #pragma unroll
            for (int i = 0; i < 4; i++) pv[i] = Ps[(ty * 4 + i) * 65 + k];
            #pragma unroll
            for (int j = 0; j < 4; j++) vv[j] = Vs[k * 65 + tx * 4 + j];
            #pragma unroll
            for (int i = 0; i < 4; i++)
                #pragma unroll
                for (int j = 0; j < 4; j++)
                    acc[i][j] = fmaf(pv[i], vv[j], acc[i][j]);
        }
    }

    // Epilogue: normalize and store to g_O in the same [token, h*64+d] layout
    #pragma unroll
    for (int i = 0; i < 4; i++) {
        float inv = 1.f / l_i[i];
        float4 o = make_float4(acc[i][0] * inv, acc[i][1] * inv,
                               acc[i][2] * inv, acc[i][3] * inv);
        *(float4*)&g_O[(qb * 64 + ty * 4 + i) * DIM + col0 + tx * 4] = o;
    }
}

// ---------------------------------------------------------------------------
extern "C" void kernel_launch(void* const* d_in, const int* in_sizes, int n_in,
                              void* d_out, int out_size) {
    const float* x  = (const float*)d_in[0];
    const float* Wq = (const float*)d_in[1];
    const float* Wk = (const float*)d_in[2];
    const float* Wv = (const float*)d_in[3];
    const float* Wo = (const float*)d_in[4];
    float* out = (float*)d_out;

    // >48KB dynamic smem opt-in (host-side attribute, capture-safe, idempotent)
    cudaFuncSetAttribute(attn_kernel,
                         cudaFuncAttributeMaxDynamicSharedMemorySize, ATT_SMEM);

    dim3 gg(DIM / 64, SEQ / 64);   // (8, 64)
    gemm_proj_kernel<<<gg, 256>>>(x, Wq, 0);
    gemm_proj_kernel<<<gg, 256>>>(x, Wk, 1);
    gemm_proj_kernel<<<gg, 256>>>(x, Wv, 2);
    attn_kernel<<<dim3(SEQ / 64, NHEAD), 256, ATT_SMEM>>>();
    gemm_out_kernel<<<gg, 256>>>(Wo, out);
}

// round 2
// speedup vs baseline: 2.3876x; 2.3876x over previous
#include <cuda_runtime.h>
#include <cstdint>

#define SEQ   4096
#define DIM   512
#define NHEAD 8
#define HD    64
#define SCALE 0.125f   // 1/sqrt(64)

// Scratch (allocation-free contract: __device__ globals)
__device__ float g_Q[SEQ * DIM];   // tf32-rounded at projection epilogue
__device__ float g_K[SEQ * DIM];   // tf32-rounded
__device__ float g_V[SEQ * DIM];   // tf32-rounded
__device__ float g_O[SEQ * DIM];   // fp32

__device__ __forceinline__ float to_tf32(float x) {
    uint32_t u;
    asm("cvt.rna.tf32.f32 %0, %1;" : "=r"(u) : "f"(x));
    return __uint_as_float(u);
}

__device__ __forceinline__ void mma_tf32(float& d0, float& d1, float& d2, float& d3,
                                         uint32_t a0, uint32_t a1, uint32_t a2, uint32_t a3,
                                         uint32_t b0, uint32_t b1) {
    asm volatile(
        "mma.sync.aligned.m16n8k8.row.col.f32.tf32.tf32.f32 "
        "{%0,%1,%2,%3}, {%4,%5,%6,%7}, {%8,%9}, {%0,%1,%2,%3};\n"
        : "+f"(d0), "+f"(d1), "+f"(d2), "+f"(d3)
        : "r"(a0), "r"(a1), "r"(a2), "r"(a3), "r"(b0), "r"(b1));
}

// ---------------------------------------------------------------------------
// GEMM: C[SEQ,DIM] = A[SEQ,DIM] @ B[DIM,DIM]^T  (fp32 FMA, unchanged engine)
// rnd != 0 -> round output to tf32 (for Q/K/V feeding the mma attention)
// ---------------------------------------------------------------------------
__device__ __forceinline__ void gemm_body(const float* __restrict__ A,
                                          const float* __restrict__ B,
                                          float* __restrict__ C, int rnd) {
    __shared__ float As[16][68];
    __shared__ float Bs[16][68];
    const int tid  = threadIdx.x;
    const int tx   = tid & 15;
    const int ty   = tid >> 4;
    const int bm   = blockIdx.y * 64;
    const int bn   = blockIdx.x * 64;
    const int lrow = tid >> 2;
    const int lk   = (tid & 3) << 2;

    const float* Ap = A + (bm + lrow) * DIM + lk;
    const float* Bp = B + (bn + lrow) * DIM + lk;

    float acc[4][4] = {};
    float4 a = *(const float4*)Ap;
    float4 b = *(const float4*)Bp;

    for (int k0 = 0; k0 < DIM; k0 += 16) {
        __syncthreads();
        As[lk + 0][lrow] = a.x; As[lk + 1][lrow] = a.y;
        As[lk + 2][lrow] = a.z; As[lk + 3][lrow] = a.w;
        Bs[lk + 0][lrow] = b.x; Bs[lk + 1][lrow] = b.y;
        Bs[lk + 2][lrow] = b.z; Bs[lk + 3][lrow] = b.w;
        __syncthreads();
        if (k0 + 16 < DIM) {
            a = *(const float4*)(Ap + k0 + 16);
            b = *(const float4*)(Bp + k0 + 16);
        }
        #pragma unroll
        for (int kk = 0; kk < 16; kk++) {
            float av[4], bv[4];
            #pragma unroll
            for (int i = 0; i < 4; i++) av[i] = As[kk][ty * 4 + i];
            #pragma unroll
            for (int j = 0; j < 4; j++) bv[j] = Bs[kk][tx * 4 + j];
            #pragma unroll
            for (int i = 0; i < 4; i++)
                #pragma unroll
                for (int j = 0; j < 4; j++)
                    acc[i][j] = fmaf(av[i], bv[j], acc[i][j]);
        }
    }
    #pragma unroll
    for (int i = 0; i < 4; i++) {
        float4 v;
        if (rnd) v = make_float4(to_tf32(acc[i][0]), to_tf32(acc[i][1]),
                                 to_tf32(acc[i][2]), to_tf32(acc[i][3]));
        else     v = make_float4(acc[i][0], acc[i][1], acc[i][2], acc[i][3]);
        *(float4*)(C + (bm + ty * 4 + i) * DIM + bn + tx * 4) = v;
    }
}

__global__ void __launch_bounds__(256)
gemm_proj_kernel(const float* __restrict__ x, const float* __restrict__ W, int dst) {
    float* C = (dst == 0) ? g_Q : (dst == 1) ? g_K : g_V;
    gemm_body(x, W, C, 1);
}

__global__ void __launch_bounds__(256)
gemm_out_kernel(const float* __restrict__ Wo, float* __restrict__ out) {
    gemm_body(g_O, Wo, out, 0);
}

// ---------------------------------------------------------------------------
// Flash attention on tf32 tensor cores (mma.sync.m16n8k8).
// Block = 128 threads (4 warps), BM=64 queries x one head; streams K/V in
// 64-key tiles. Warp w owns query strip rows [w*16, w*16+16).
// Smem strides chosen so every fragment LDS is 32-bank conflict-free.
// ---------------------------------------------------------------------------
#define KSS 68   // Ks stride: bank = 4g+t, all distinct
#define VSS 72   // Vs stride: bank = 8t+g, all distinct
#define PSS 68   // Ps stride: bank = 4g+t, all distinct
#define ATT_SMEM ((64 * KSS + 64 * VSS + 64 * PSS) * (int)sizeof(float))  // 53248 B

__global__ void __launch_bounds__(128, 4) attn_mma_kernel() {
    extern __shared__ float sm[];
    float* Ks = sm;                    // [64][KSS]  (key, d)
    float* Vs = Ks + 64 * KSS;         // [64][VSS]  (key, d)
    float* Ps = Vs + 64 * VSS;         // [64][PSS]  (q, key) tf32-rounded

    const int tid  = threadIdx.x;
    const int lane = tid & 31;
    const int w    = tid >> 5;         // warp 0..3
    const int g    = lane >> 2;        // 0..7
    const int t    = lane & 3;         // 0..3
    const int qb   = blockIdx.x;
    const int h    = blockIdx.y;
    const int col0 = h * HD;
    const int row0 = qb * 64 + w * 16 + g;   // global q row for a0/a2 lanes

    // --- Preload Q fragments (held in registers for all 64 iterations) ---
    const uint32_t* Qg = (const uint32_t*)g_Q;
    uint32_t qf[8][4];
    {
        const int base_lo = row0 * DIM + col0;
        const int base_hi = (row0 + 8) * DIM + col0;
        #pragma unroll
        for (int s = 0; s < 8; s++) {
            qf[s][0] = Qg[base_lo + 8 * s + t];
            qf[s][1] = Qg[base_hi + 8 * s + t];
            qf[s][2] = Qg[base_lo + 8 * s + t + 4];
            qf[s][3] = Qg[base_hi + 8 * s + t + 4];
        }
    }

    float o[8][4] = {};
    float m_i[2] = {-1e30f, -1e30f};
    float l_i[2] = {0.f, 0.f};

    for (int kb = 0; kb < SEQ / 64; kb++) {
        __syncthreads();   // previous iteration's Ks/Vs consumers done
        // --- Load K/V tile (64x64 each), already tf32-rounded in gmem ---
        #pragma unroll
        for (int it = 0; it < 8; it++) {
            int idx = tid + it * 128;
            int r   = idx >> 4;
            int c4  = (idx & 15) << 2;
            int gofs = (kb * 64 + r) * DIM + col0 + c4;
            *(float4*)&Ks[r * KSS + c4] = *(const float4*)&g_K[gofs];
            *(float4*)&Vs[r * VSS + c4] = *(const float4*)&g_V[gofs];
        }
        __syncthreads();

        // --- S = Q @ K^T  (per warp: m16 x n64 x k64) ---
        float sf[8][4] = {};
        #pragma unroll
        for (int s = 0; s < 8; s++) {
            #pragma unroll
            for (int j = 0; j < 8; j++) {
                uint32_t b0 = __float_as_uint(Ks[(8 * j + g) * KSS + 8 * s + t]);
                uint32_t b1 = __float_as_uint(Ks[(8 * j + g) * KSS + 8 * s + t + 4]);
                mma_tf32(sf[j][0], sf[j][1], sf[j][2], sf[j][3],
                         qf[s][0], qf[s][1], qf[s][2], qf[s][3], b0, b1);
            }
        }

        // --- Online softmax (rows w*16+g and w*16+g+8; quad = 4 lanes/row) ---
        #pragma unroll
        for (int half = 0; half < 2; half++) {
            float mx = -1e30f;
            #pragma unroll
            for (int j = 0; j < 8; j++) {
                sf[j][2 * half]     *= SCALE;
                sf[j][2 * half + 1] *= SCALE;
                mx = fmaxf(mx, fmaxf(sf[j][2 * half], sf[j][2 * half + 1]));
            }
            mx = fmaxf(mx, __shfl_xor_sync(0xffffffffu, mx, 1));
            mx = fmaxf(mx, __shfl_xor_sync(0xffffffffu, mx, 2));
            float m_new = fmaxf(m_i[half], mx);
            float alpha = __expf(m_i[half] - m_new);
            float rs = 0.f;
            float* prow = Ps + (w * 16 + g + 8 * half) * PSS;
            #pragma unroll
            for (int j = 0; j < 8; j++) {
                float p0 = __expf(sf[j][2 * half]     - m_new);
                float p1 = __expf(sf[j][2 * half + 1] - m_new);
                rs += p0 + p1;
                uint32_t u0, u1;
                asm("cvt.rna.tf32.f32 %0, %1;" : "=r"(u0) : "f"(p0));
                asm("cvt.rna.tf32.f32 %0, %1;" : "=r"(u1) : "f"(p1));
                *(uint2*)(prow + 8 * j + 2 * t) = make_uint2(u0, u1);
            }
            rs += __shfl_xor_sync(0xffffffffu, rs, 1);
            rs += __shfl_xor_sync(0xffffffffu, rs, 2);
            l_i[half] = l_i[half] * alpha + rs;
            m_i[half] = m_new;
            #pragma unroll
            for (int j = 0; j < 8; j++) {
                o[j][2 * half]     *= alpha;
                o[j][2 * half + 1] *= alpha;
            }
        }
        __syncwarp();   // P strip is warp-private; order STS -> LDS across lanes

        // --- O += P @ V  (per warp: m16 x n64 x k64, k = keys) ---
        #pragma unroll
        for (int s = 0; s < 8; s++) {
            uint32_t a0 = __float_as_uint(Ps[(w * 16 + g) * PSS + 8 * s + t]);
            uint32_t a1 = __float_as_uint(Ps[(w * 16 + g + 8) * PSS + 8 * s + t]);
            uint32_t a2 = __float_as_uint(Ps[(w * 16 + g) * PSS + 8 * s + t + 4]);
            uint32_t a3 = __float_as_uint(Ps[(w * 16 + g + 8) * PSS + 8 * s + t + 4]);
            #pragma unroll
            for (int j = 0; j < 8; j++) {
                uint32_t b0 = __float_as_uint(Vs[(8 * s + t) * VSS + 8 * j + g]);
                uint32_t b1 = __float_as_uint(Vs[(8 * s + t + 4) * VSS + 8 * j + g]);
                mma_tf32(o[j][0], o[j][1], o[j][2], o[j][3],
                         a0, a1, a2, a3, b0, b1);
            }
        }
    }

    // --- Epilogue: normalize, write g_O (fp32) ---
    float inv0 = 1.f / l_i[0];
    float inv1 = 1.f / l_i[1];
    #pragma unroll
    for (int j = 0; j < 8; j++) {
        *(float2*)&g_O[row0 * DIM + col0 + 8 * j + 2 * t] =
            make_float2(o[j][0] * inv0, o[j][1] * inv0);
        *(float2*)&g_O[(row0 + 8) * DIM + col0 + 8 * j + 2 * t] =
            make_float2(o[j][2] * inv1, o[j][3] * inv1);
    }
}

// ---------------------------------------------------------------------------
extern "C" void kernel_launch(void* const* d_in, const int* in_sizes, int n_in,
                              void* d_out, int out_size) {
    const float* x  = (const float*)d_in[0];
    const float* Wq = (const float*)d_in[1];
    const float* Wk = (const float*)d_in[2];
    const float* Wv = (const float*)d_in[3];
    const float* Wo = (const float*)d_in[4];
    float* out = (float*)d_out;

    cudaFuncSetAttribute(attn_mma_kernel,
                         cudaFuncAttributeMaxDynamicSharedMemorySize, ATT_SMEM);

    dim3 gg(DIM / 64, SEQ / 64);   // (8, 64)
    gemm_proj_kernel<<<gg, 256>>>(x, Wq, 0);
    gemm_proj_kernel<<<gg, 256>>>(x, Wk, 1);
    gemm_proj_kernel<<<gg, 256>>>(x, Wv, 2);
    attn_mma_kernel<<<dim3(SEQ / 64, NHEAD), 128, ATT_SMEM>>>();
    gemm_out_kernel<<<gg, 256>>>(Wo, out);
}